// round 17
// baseline (speedup 1.0000x reference)
#include <cuda_runtime.h>
#include <cuda_fp16.h>
#include <cstdint>

// ---------------- problem dims ----------------
#define Lq   2048
#define Hd   2048
#define Id   4096
#define Nst  16
#define Rdt  128
#define PROJ2 (2*Id)   // 8192
#define SSW  (Rdt + 2*Nst)   // 160
#define KSPL 8               // split-K factor for x_proj GEMM
#define OSPL 4               // split-K factor for out GEMM
#define NCH  32              // scan chunks
#define CHL  64              // steps per chunk (NCH*CHL == Lq)

// ---------------- scratch ----------------
__device__ __align__(16) __half g_proj_h[Lq * PROJ2];  // hidden | gate (fp16)
__device__ float g_ssm [Lq * SSW];            // dt_in|B|C
__device__ float g_ssm_part[KSPL * Lq * SSW]; // split-K partials (x_proj)
__device__ float g_out_part[OSPL * Lq * Hd];  // split-K partials (out)
__device__ float g_dt  [Lq * Id];             // softplus dt
__device__ float g_P   [NCH * Id * Nst];
__device__ float g_S   [NCH * Id * Nst];
__device__ float g_init[NCH * Id * Nst];

// ---------------- fp16 GEMM operands ----------------
__device__ __align__(16) __half g_in_h  [Lq * Hd];       // hi only
__device__ __align__(16) __half g_win_h [PROJ2 * Hd];    // hi only
__device__ __align__(16) __half g_u_h   [Lq * 2*Id];     // [hi|lo]
__device__ __align__(16) __half g_wx_h  [256 * Id];      // hi only (pad 160->256)
__device__ __align__(16) __half g_dtin_h[Lq * 2*Rdt];    // [hi|lo]
__device__ __align__(16) __half g_wdt_h [Id * Rdt];      // hi only
__device__ __align__(16) __half g_y_h   [Lq * Id];       // hi only
__device__ __align__(16) __half g_wout_h[Hd * Id];       // hi only

// ---------------- PTX helpers ----------------
__device__ __forceinline__ uint32_t smem_u32(const void* p) {
    uint32_t a;
    asm("{ .reg .u64 t; cvta.to.shared.u64 t, %1; cvt.u32.u64 %0, t; }"
        : "=r"(a) : "l"(p));
    return a;
}
__device__ __forceinline__ void cp16(uint32_t dst, const void* src) {
    asm volatile("cp.async.cg.shared.global [%0], [%1], 16;"
                 :: "r"(dst), "l"(src));
}
__device__ __forceinline__ void ldm4(uint32_t* r, uint32_t addr) {
    asm volatile("ldmatrix.sync.aligned.m8n8.x4.shared.b16 {%0,%1,%2,%3}, [%4];"
                 : "=r"(r[0]), "=r"(r[1]), "=r"(r[2]), "=r"(r[3]) : "r"(addr));
}
__device__ __forceinline__ void mma16816(float* d, const uint32_t* a, const uint32_t* b) {
    asm volatile(
        "mma.sync.aligned.m16n8k16.row.col.f32.f16.f16.f32 "
        "{%0,%1,%2,%3}, {%4,%5,%6,%7}, {%8,%9}, {%0,%1,%2,%3};"
        : "+f"(d[0]), "+f"(d[1]), "+f"(d[2]), "+f"(d[3])
        : "r"(a[0]), "r"(a[1]), "r"(a[2]), "r"(a[3]), "r"(b[0]), "r"(b[1]));
}

// ============ fp16 HMMA GEMM: C = A[M,K3] @ B[N, ldb]^T, B chunks wrap ============
// 256 threads, 8 warps (4M x 2N of 32x64 warp tiles), 2 CTAs/SM -> 16 warps/SM.
// Race-free double-chunk mainloop: barrier A (overwrite-safe), loads, wait,
// barrier B (publish), then reads incl. cross-iteration prefetch.
// EPI: 0 none, 1 bias+softplus. OUTH: 1 = store fp16 (__half2), 0 = fp32.
static constexpr int STAGE_B = 16384;          // 8KB A + 8KB B
static constexpr int NSTG    = 6;
static constexpr int GSMEM   = NSTG * STAGE_B; // 98304

template<int EPI, int OUTH>
__global__ __launch_bounds__(256, 2)
void hmma_gemm(const __half* __restrict__ A, const __half* __restrict__ B,
               void* __restrict__ Cv, const float* __restrict__ bias,
               int N, int K3, int ldb, int nkb, int ldc, int nks, int sliceC)
{
    extern __shared__ __align__(16) char smem[];

    const int tid = threadIdx.x, wid = tid >> 5, lane = tid & 31;
    const int rowBase = blockIdx.x * 128;
    const int colBase = blockIdx.y * 128;
    const int wm = wid >> 1, wn = wid & 1;      // warp tile: 32M x 64N

    float acc[2][8][4] = {};

    const int k0ch = blockIdx.z * nks;
    float* C = (float*)Cv + (size_t)blockIdx.z * sliceC;

    const int r0 = tid >> 2, cc = tid & 3;      // r0: 0..63
    const uint32_t soff = (uint32_t)((cc ^ ((r0 >> 1) & 3)) << 4);
    const __half* aP = A + (size_t)(rowBase + r0) * K3 + (size_t)k0ch * 32 + cc * 8;
    const __half* bP = B + (size_t)(colBase + r0) * ldb + cc * 8;
    const uint32_t sBase = smem_u32(smem);

    auto loadStage = [&](int s, int ck) {
        const uint32_t as = sBase + s * STAGE_B;
        const uint32_t bs = as + 8192;
        const size_t koA = (size_t)ck * 32;
        int kabs = k0ch + ck;
        if (kabs >= nkb) kabs -= nkb;           // B wraps (hi reused)
        const size_t koB = (size_t)kabs * 32;
        #pragma unroll
        for (int i = 0; i < 2; i++) {
            const uint32_t d = (uint32_t)((r0 + 64 * i) * 64) + soff;
            cp16(as + d, aP + koA + (size_t)(64 * i) * K3);
            cp16(bs + d, bP + koB + (size_t)(64 * i) * ldb);
        }
        asm volatile("cp.async.commit_group;");
    };

    auto loadFrags = [&](uint32_t stageAddr, int ks,
                         uint32_t af[2][4], uint32_t bfr[4][4]) {
        const uint32_t aB = stageAddr, bB = stageAddr + 8192;
        #pragma unroll
        for (int mt = 0; mt < 2; mt++) {
            int row = wm * 32 + mt * 16 + (lane & 15);
            int c2  = ks * 2 + (lane >> 4);
            ldm4(af[mt], aB + (uint32_t)(row * 64) +
                         (uint32_t)((c2 ^ ((row >> 1) & 3)) << 4));
        }
        #pragma unroll
        for (int nb = 0; nb < 4; nb++) {
            int row = wn * 64 + nb * 16 + (lane & 7) + ((lane >> 4) << 3);
            int c2  = ks * 2 + ((lane >> 3) & 1);
            ldm4(bfr[nb], bB + (uint32_t)(row * 64) +
                          (uint32_t)((c2 ^ ((row >> 1) & 3)) << 4));
        }
    };

    #define DOMMA(F, FB) \
        _Pragma("unroll") \
        for (int mt = 0; mt < 2; mt++) \
            _Pragma("unroll") \
            for (int nt = 0; nt < 8; nt++) \
                mma16816(acc[mt][nt], F[mt], &FB[nt >> 1][(nt & 1) * 2]);

    // prologue: 4 chunks (all GEMMs have even nks >= 4)
    #pragma unroll
    for (int s0 = 0; s0 < 4; s0++) loadStage(s0, s0);
    asm volatile("cp.async.wait_group 2;");   // chunks 0,1 resident (this thread)
    __syncthreads();                          // publish to all threads

    uint32_t fa[2][4], fab[4][4];             // ks0 frags of chunk ck
    loadFrags(sBase, 0, fa, fab);

    int s0i = 0;                              // stage of chunk ck
    for (int ck = 0; ck < nks; ck += 2) {
        __syncthreads();                      // A: all reads of old stages done
        if (ck + 4 < nks) {
            loadStage((s0i + 4) % NSTG, ck + 4);
            loadStage((s0i + 5) % NSTG, ck + 5);
        } else {
            asm volatile("cp.async.commit_group;");
            asm volatile("cp.async.commit_group;");
        }
        asm volatile("cp.async.wait_group 2;");   // chunks ck..ck+3 done (this thread)
        __syncthreads();                          // B: published to all threads

        const uint32_t st0 = sBase + s0i * STAGE_B;
        const uint32_t st1 = sBase + ((s0i + 1) % NSTG) * STAGE_B;

        uint32_t fb[2][4], fbb[4][4];
        loadFrags(st0, 1, fb, fbb);               // (ck, ks1)
        DOMMA(fa, fab);
        loadFrags(st1, 0, fa, fab);               // (ck+1, ks0)
        DOMMA(fb, fbb);
        loadFrags(st1, 1, fb, fbb);               // (ck+1, ks1)
        DOMMA(fa, fab);
        if (ck + 2 < nks) {                       // (ck+2, ks0) — published by B
            const uint32_t st2 = sBase + ((s0i + 2) % NSTG) * STAGE_B;
            loadFrags(st2, 0, fa, fab);
        }
        DOMMA(fb, fbb);

        s0i += 2; if (s0i >= NSTG) s0i -= NSTG;
    }
    #undef DOMMA

    #pragma unroll
    for (int mt = 0; mt < 2; mt++) {
        #pragma unroll
        for (int nt = 0; nt < 8; nt++) {
            int col = colBase + wn * 64 + nt * 8 + (lane & 3) * 2;
            if (col >= N) continue;
            #pragma unroll
            for (int h = 0; h < 2; h++) {
                int row = rowBase + wm * 32 + mt * 16 + (lane >> 2) + h * 8;
                float v0 = acc[mt][nt][h * 2 + 0];
                float v1 = acc[mt][nt][h * 2 + 1];
                if (EPI == 1) {
                    v0 += bias[col];
                    v1 += bias[col + 1];
                    v0 = (v0 > 20.f) ? v0 : log1pf(__expf(v0));
                    v1 = (v1 > 20.f) ? v1 : log1pf(__expf(v1));
                }
                if (OUTH) {
                    __half* Ch = (__half*)Cv;
                    *(__half2*)&Ch[(size_t)row * ldc + col] =
                        __halves2half2(__float2half(v0), __float2half(v1));
                } else {
                    *(float2*)&C[(size_t)row * ldc + col] = make_float2(v0, v1);
                }
            }
        }
    }
}

// ==== split-K reduce, fused with dtin fp16 2-term split ====
__global__ __launch_bounds__(256)
void reduceK_split(float* __restrict__ dst, const float* __restrict__ parts,
                   __half* __restrict__ dtin, int n)
{
    int idx = blockIdx.x * 256 + threadIdx.x;
    if (idx >= n) return;
    float s = parts[idx];
    #pragma unroll
    for (int z = 1; z < KSPL; z++) s += parts[(size_t)z * n + idx];
    dst[idx] = s;
    int t = idx / SSW, k = idx - t * SSW;
    if (k < Rdt) {
        __half h = __float2half(s);
        __half l = __float2half(s - __half2float(h));
        size_t base = (size_t)t * (2 * Rdt);
        dtin[base + k] = h;
        dtin[base + Rdt + k] = l;
    }
}

// ==== out split-K reduce (OSPL slices) ====
__global__ __launch_bounds__(256)
void reduceOut(float* __restrict__ dst, const float* __restrict__ parts, int n)
{
    int idx = blockIdx.x * 256 + threadIdx.x;
    if (idx >= n) return;
    float s = parts[idx];
    #pragma unroll
    for (int z = 1; z < OSPL; z++) s += parts[(size_t)z * n + idx];
    dst[idx] = s;
}

// ============ consolidated conversion kernel ============
__device__ __forceinline__
void wsplitT_h_body(const float* W, __half* Y, int K, int N, int bx, int by,
                    float (*tile)[33], int tx, int ty)
{
    int n0 = bx * 32, k0 = by * 32;
    for (int i = ty; i < 32; i += 8) {
        int n = n0 + tx;
        tile[i][tx] = (n < N) ? W[(size_t)(k0 + i) * N + n] : 0.f;
    }
    __syncthreads();
    for (int i = ty; i < 32; i += 8) {
        int n = n0 + i;
        int k = k0 + tx;
        Y[(size_t)n * K + k] = __float2half(tile[tx][i]);
    }
}

static constexpr int NB_AS  = (Lq * Hd) / 256;              // 16384
static constexpr int NB_WIN = (PROJ2 / 32) * (Hd / 32);     // 16384
static constexpr int NB_WX  = (256 / 32) * (Id / 32);       // 1024
static constexpr int NB_WDT = (Id / 32) * (Rdt / 32);       // 512
static constexpr int NB_WO  = (Hd / 32) * (Id / 32);        // 8192

__global__ __launch_bounds__(256)
void convertAll(const float* __restrict__ input,
                const float* __restrict__ in_proj_w,
                const float* __restrict__ x_proj_w,
                const float* __restrict__ dt_proj_w,
                const float* __restrict__ out_proj_w)
{
    __shared__ float tile[32][33];
    int b = blockIdx.x;
    int tid = threadIdx.x;
    int tx = tid & 31, ty = tid >> 5;

    if (b < NB_AS) {
        int idx = b * 256 + tid;
        g_in_h[idx] = __float2half(input[idx]);
        return;
    }
    b -= NB_AS;
    if (b < NB_WIN) {
        wsplitT_h_body(in_proj_w, g_win_h, Hd, PROJ2,
                       b & 255, b >> 8, tile, tx, ty);
        return;
    }
    b -= NB_WIN;
    if (b < NB_WX) {
        wsplitT_h_body(x_proj_w, g_wx_h, Id, SSW,
                       b & 7, b >> 3, tile, tx, ty);
        return;
    }
    b -= NB_WX;
    if (b < NB_WDT) {
        wsplitT_h_body(dt_proj_w, g_wdt_h, Rdt, Id,
                       b & 127, b >> 7, tile, tx, ty);
        return;
    }
    b -= NB_WDT;
    wsplitT_h_body(out_proj_w, g_wout_h, Id, Hd,
                   b & 63, b >> 6, tile, tx, ty);
}

// ===== conv v2: smem-tiled depthwise causal conv (K=4) + SiLU =====
__global__ __launch_bounds__(256)
void conv_silu_kernel(const float* __restrict__ conv_w,
                      const float* __restrict__ conv_b)
{
    __shared__ __half hid[67][64];
    const int i0 = blockIdx.x * 64, t0 = blockIdx.y * 64;
    const int tid = threadIdx.x;
    const int tx = tid & 63, ty = tid >> 6;    // ty: 0..3

    for (int idx = tid; idx < 67 * 64; idx += 256) {
        int tr = idx >> 6, j = idx & 63;
        int t = t0 - 3 + tr;
        hid[tr][j] = (t >= 0) ? g_proj_h[(size_t)t * PROJ2 + i0 + j]
                              : __float2half(0.f);
    }
    __syncthreads();

    const int i = i0 + tx;
    const float4 w = *(const float4*)(conv_w + i * 4);
    const float bv = conv_b[i];

    #pragma unroll 4
    for (int r = 0; r < 16; r++) {
        int tl = ty * 16 + r;
        float acc = bv;
        acc = fmaf(w.x, __half2float(hid[tl + 0][tx]), acc);
        acc = fmaf(w.y, __half2float(hid[tl + 1][tx]), acc);
        acc = fmaf(w.z, __half2float(hid[tl + 2][tx]), acc);
        acc = fmaf(w.w, __half2float(hid[tl + 3][tx]), acc);
        float s = acc / (1.f + __expf(-acc));
        __half h = __float2half(s);
        __half l = __float2half(s - __half2float(h));
        size_t base = (size_t)(t0 + tl) * (2 * Id);
        g_u_h[base + i] = h;
        g_u_h[base + Id + i] = l;
    }
}

// ================= chunked parallel scan (smem-staged, CHL=64) =================
__global__ __launch_bounds__(256)
void scanA(const float* __restrict__ A_log)
{
    __shared__ float dt_s[CHL][16], u_s[CHL][16], bn_s[CHL][16];
    const int bi = blockIdx.x & 255, c = blockIdx.x >> 8;
    const int i0 = bi * 16, t0 = c * CHL;
    const int tid = threadIdx.x, ii = tid >> 4, n = tid & 15;

    #pragma unroll 4
    for (int k = tid; k < CHL * 16; k += 256) {
        int t = k >> 4, j = k & 15;
        dt_s[t][j] = g_dt[(size_t)(t0 + t) * Id + i0 + j];
        size_t ub = (size_t)(t0 + t) * (2 * Id) + i0 + j;
        u_s [t][j] = __half2float(g_u_h[ub]) + __half2float(g_u_h[ub + Id]);
        bn_s[t][j] = g_ssm[(t0 + t) * SSW + Rdt + j];
    }
    __syncthreads();

    float a = -__expf(A_log[(i0 + ii) * Nst + n]);
    float P = 1.f, S = 0.f;
    #pragma unroll 4
    for (int t = 0; t < CHL; t++) {
        float dA = __expf(dt_s[t][ii] * a);
        S = fmaf(S, dA, dt_s[t][ii] * u_s[t][ii] * bn_s[t][n]);
        P *= dA;
    }
    int idx = c * (Id * Nst) + (i0 + ii) * Nst + n;
    g_P[idx] = P;
    g_S[idx] = S;
}

__global__ __launch_bounds__(256)
void scanB()
{
    int k = blockIdx.x * 256 + threadIdx.x;   // i*16+n
    float s = 0.f;
    #pragma unroll 4
    for (int c = 0; c < NCH; c++) {
        g_init[c * (Id * Nst) + k] = s;
        s = fmaf(s, g_P[c * (Id * Nst) + k], g_S[c * (Id * Nst) + k]);
    }
}

__global__ __launch_bounds__(256)
void scanC(const float* __restrict__ A_log, const float* __restrict__ Dp)
{
    __shared__ float dt_s[CHL][16], u_s[CHL][16], bn_s[CHL][16],
                     cn_s[CHL][16], gt_s[CHL][16], y_s[CHL][16];
    const int bi = blockIdx.x & 255, c = blockIdx.x >> 8;
    const int i0 = bi * 16, t0 = c * CHL;
    const int tid = threadIdx.x, ii = tid >> 4, n = tid & 15;

    #pragma unroll 4
    for (int k = tid; k < CHL * 16; k += 256) {
        int t = k >> 4, j = k & 15;
        dt_s[t][j] = g_dt[(size_t)(t0 + t) * Id + i0 + j];
        size_t ub = (size_t)(t0 + t) * (2 * Id) + i0 + j;
        u_s [t][j] = __half2float(g_u_h[ub]) + __half2float(g_u_h[ub + Id]);
        bn_s[t][j] = g_ssm[(t0 + t) * SSW + Rdt + j];
        cn_s[t][j] = g_ssm[(t0 + t) * SSW + Rdt + Nst + j];
        gt_s[t][j] = __half2float(g_proj_h[(size_t)(t0 + t) * PROJ2 + Id + i0 + j]);
    }
    __syncthreads();

    float a  = -__expf(A_log[(i0 + ii) * Nst + n]);
    float dv = Dp[i0 + ii];
    int idx = c * (Id * Nst) + (i0 + ii) * Nst + n;
    float state = g_init[idx];
    #pragma unroll 2
    for (int t = 0; t < CHL; t++) {
        float dtv = dt_s[t][ii];
        float uv  = u_s[t][ii];
        float dA = __expf(dtv * a);
        state = fmaf(state, dA, dtv * uv * bn_s[t][n]);
        float p = state * cn_s[t][n];
        p += __shfl_xor_sync(0xffffffffu, p, 1);
        p += __shfl_xor_sync(0xffffffffu, p, 2);
        p += __shfl_xor_sync(0xffffffffu, p, 4);
        p += __shfl_xor_sync(0xffffffffu, p, 8);
        if (n == 0) {
            float gate = gt_s[t][ii];
            float sg = gate / (1.f + __expf(-gate));
            y_s[t][ii] = (p + uv * dv) * sg;
        }
    }
    __syncthreads();

    #pragma unroll 4
    for (int k = tid; k < CHL * 16; k += 256) {
        int t = k >> 4, j = k & 15;
        g_y_h[(size_t)(t0 + t) * Id + i0 + j] = __float2half(y_s[t][j]);
    }
}

// ==================== launcher (single stream, 11 launches) ====================
extern "C" void kernel_launch(void* const* d_in, const int* in_sizes, int n_in,
                              void* d_out, int out_size)
{
    const float* input      = (const float*)d_in[0];
    const float* in_proj_w  = (const float*)d_in[1];
    const float* conv_w     = (const float*)d_in[2];
    const float* conv_b     = (const float*)d_in[3];
    const float* x_proj_w   = (const float*)d_in[4];
    const float* dt_proj_w  = (const float*)d_in[5];
    const float* dt_proj_b  = (const float*)d_in[6];
    const float* A_log      = (const float*)d_in[7];
    const float* Dp         = (const float*)d_in[8];
    const float* out_proj_w = (const float*)d_in[9];
    float* out = (float*)d_out;

    float *ssm, *ssm_part, *out_part, *dt;
    cudaGetSymbolAddress((void**)&ssm,      g_ssm);
    cudaGetSymbolAddress((void**)&ssm_part, g_ssm_part);
    cudaGetSymbolAddress((void**)&out_part, g_out_part);
    cudaGetSymbolAddress((void**)&dt,       g_dt);
    __half *proj_h, *in_h, *win_h, *u_h, *wx_h, *dtin_h, *wdt_h, *y_h, *wout_h;
    cudaGetSymbolAddress((void**)&proj_h, g_proj_h);
    cudaGetSymbolAddress((void**)&in_h,   g_in_h);
    cudaGetSymbolAddress((void**)&win_h,  g_win_h);
    cudaGetSymbolAddress((void**)&u_h,    g_u_h);
    cudaGetSymbolAddress((void**)&wx_h,   g_wx_h);
    cudaGetSymbolAddress((void**)&dtin_h, g_dtin_h);
    cudaGetSymbolAddress((void**)&wdt_h,  g_wdt_h);
    cudaGetSymbolAddress((void**)&y_h,    g_y_h);
    cudaGetSymbolAddress((void**)&wout_h, g_wout_h);

    cudaFuncSetAttribute((const void*)hmma_gemm<0, 0>,
                         cudaFuncAttributeMaxDynamicSharedMemorySize, GSMEM);
    cudaFuncSetAttribute((const void*)hmma_gemm<0, 1>,
                         cudaFuncAttributeMaxDynamicSharedMemorySize, GSMEM);
    cudaFuncSetAttribute((const void*)hmma_gemm<1, 0>,
                         cudaFuncAttributeMaxDynamicSharedMemorySize, GSMEM);

    const int NB_ALL = NB_AS + NB_WIN + NB_WX + NB_WDT + NB_WO;

    // [0] ALL input conversions
    convertAll<<<NB_ALL, 256>>>(input, in_proj_w, x_proj_w, dt_proj_w, out_proj_w);

    // [1] GEMM1: proj = input @ in_proj_w (hi-only, fp16 output)
    hmma_gemm<0, 1><<<dim3(Lq / 128, PROJ2 / 128), 256, GSMEM>>>(
        in_h, win_h, proj_h, (const float*)nullptr, PROJ2,
        Hd, Hd, Hd / 32, PROJ2, Hd / 32, 0);

    // [2] conv + SiLU -> u fp16 [hi|lo]
    conv_silu_kernel<<<dim3(Id / 64, Lq / 64), 256>>>(conv_w, conv_b);

    // [3] ssm_in = u @ x_proj_w : A=[hi|lo] K3=2*Id, B hi wraps; split-K=8
    hmma_gemm<0, 0><<<dim3(Lq / 128, 2, KSPL), 256, GSMEM>>>(
        u_h, wx_h, ssm_part, (const float*)nullptr, SSW,
        2 * Id, Id, Id / 32, SSW, (2 * Id) / 32 / KSPL, Lq * SSW);

    // [4] reduce + fused dtin fp16 split
    reduceK_split<<<(Lq * SSW + 255) / 256, 256>>>(ssm, ssm_part, dtin_h, Lq * SSW);

    // [5] dt = softplus(dtin @ dt_proj_w + b)
    hmma_gemm<1, 0><<<dim3(Lq / 128, Id / 128), 256, GSMEM>>>(
        dtin_h, wdt_h, dt, dt_proj_b, Id,
        2 * Rdt, Rdt, Rdt / 32, Id, (2 * Rdt) / 32, 0);

    // [6..8] chunked parallel scan
    scanA<<<(Id / 16) * NCH, 256>>>(A_log);
    scanB<<<(Id * Nst) / 256, 256>>>();
    scanC<<<(Id / 16) * NCH, 256>>>(A_log, Dp);

    // [9] out = y @ out_proj_w : split-K=4 partials
    hmma_gemm<0, 0><<<dim3(Lq / 128, Hd / 128, OSPL), 256, GSMEM>>>(
        y_h, wout_h, out_part, (const float*)nullptr, Hd,
        Id, Id, Id / 32, Hd, Id / 32 / OSPL, Lq * Hd);

    // [10] final reduce into d_out
    reduceOut<<<(Lq * Hd + 255) / 256, 256>>>(out, out_part, Lq * Hd);
}